// round 5
// baseline (speedup 1.0000x reference)
#include <cuda_runtime.h>

#define DI __device__ __forceinline__

namespace {
constexpr int Bsz = 2;
constexpr int Nq  = 4096;
constexpr int Nkv = 4096;
constexpr int ENC = 768;
constexpr int DEC = 512;
constexpr int NH  = 8;
constexpr int HD  = 64;
constexpr float SCALE = 0.125f;  // 64^-0.5
}

// Scratch (allocation-free: static device globals)
__device__ float g_q[(size_t)Bsz * NH * Nq  * HD];  // [B,H,N,64]
__device__ float g_k[(size_t)Bsz * NH * Nkv * HD];  // [B,H,Ny,64]
__device__ float g_v[(size_t)Bsz * NH * Nkv * HD];  // [B,H,Ny,64]
__device__ float g_o[(size_t)Bsz * Nq * DEC];       // [B,N,512]

// ---------------------------------------------------------------------------
// GEMM-NT: C[m][n] = sum_k A[m][k] * Bw[n][k]  (both row-major)
// 64x64 tile, BK=16, 256 threads, 4x4 frags.
// MODE 0: A=x,  write g_q with head reshuffle
// MODE 1: A=y,  write g_k / g_v split with head reshuffle
// MODE 2: A=g_o, write Cout + bias
// ---------------------------------------------------------------------------
template<int MODE, int K>
__global__ __launch_bounds__(256) void gemm_nt(const float* __restrict__ A,
                                               const float* __restrict__ Bw,
                                               float* __restrict__ Cout,
                                               const float* __restrict__ bias)
{
    __shared__ __align__(16) float As[16][68];
    __shared__ __align__(16) float Bs[16][68];
    const int tid = threadIdx.x;
    const int tx = tid & 15, ty = tid >> 4;
    const int m0 = blockIdx.y * 64;
    const int n0 = blockIdx.x * 64;
    const int lrow = tid >> 2;          // 0..63
    const int lk   = (tid & 3) << 2;    // 0,4,8,12

    const float* Abase = (MODE == 2) ? g_o : A;
    const float* aptr = Abase + (size_t)(m0 + lrow) * K + lk;
    const float* bptr = Bw    + (size_t)(n0 + lrow) * K + lk;

    float acc[4][4] = {};

    for (int k0 = 0; k0 < K; k0 += 16) {
        float4 av = *(const float4*)(aptr + k0);
        float4 bv = *(const float4*)(bptr + k0);
        __syncthreads();
        As[lk+0][lrow] = av.x; As[lk+1][lrow] = av.y;
        As[lk+2][lrow] = av.z; As[lk+3][lrow] = av.w;
        Bs[lk+0][lrow] = bv.x; Bs[lk+1][lrow] = bv.y;
        Bs[lk+2][lrow] = bv.z; Bs[lk+3][lrow] = bv.w;
        __syncthreads();
        #pragma unroll
        for (int k = 0; k < 16; ++k) {
            float4 a = *(const float4*)&As[k][ty << 2];
            float4 b = *(const float4*)&Bs[k][tx << 2];
            float ar[4] = {a.x, a.y, a.z, a.w};
            float br[4] = {b.x, b.y, b.z, b.w};
            #pragma unroll
            for (int i = 0; i < 4; ++i)
                #pragma unroll
                for (int j = 0; j < 4; ++j)
                    acc[i][j] = fmaf(ar[i], br[j], acc[i][j]);
        }
    }

    #pragma unroll
    for (int i = 0; i < 4; ++i) {
        const int m = m0 + (ty << 2) + i;
        #pragma unroll
        for (int j = 0; j < 4; ++j) {
            const int n = n0 + (tx << 2) + j;
            const float v = acc[i][j];
            if (MODE == 0) {
                const int b = m >> 12, nn = m & 4095, h = n >> 6, d = n & 63;
                g_q[(((size_t)(b * NH + h)) * Nq + nn) * HD + d] = v;
            } else if (MODE == 1) {
                const int b = m >> 12, nn = m & 4095;
                if (n < DEC) {
                    const int h = n >> 6, d = n & 63;
                    g_k[(((size_t)(b * NH + h)) * Nkv + nn) * HD + d] = v;
                } else {
                    const int n2 = n - DEC, h = n2 >> 6, d = n2 & 63;
                    g_v[(((size_t)(b * NH + h)) * Nkv + nn) * HD + d] = v;
                }
            } else {
                Cout[(size_t)m * DEC + n] = v + bias[n];
            }
        }
    }
}

// ---------------------------------------------------------------------------
// Fused flash-attention, fp32.
// Grid: (N/64, B*H). Block 256 threads (16x16), 4x4 frags.
// Smem: Qs (64x64, transposed+swizzled), KPs (K transposed / P, shared buffer),
//       Vs (64x64 plain). Exactly 48 KB static.
// ---------------------------------------------------------------------------
DI int swz(int a, int b) {              // scalar element [a][b] in 64x64
    const int ph = (b >> 2) ^ ((a >> 2) & 15);
    return a * 64 + (ph << 2) + (b & 3);
}
DI const float4* swp4(const float* base, int a, int b4) {  // float4 group b4
    const int ph = b4 ^ ((a >> 2) & 15);
    return (const float4*)(base + a * 64 + (ph << 2));
}

__global__ __launch_bounds__(256) void attn_kernel(const int* __restrict__ kpm)
{
    __shared__ __align__(16) float Qs[64 * 64];
    __shared__ __align__(16) float KPs[64 * 64];
    __shared__ __align__(16) float Vs[64 * 64];

    const int tid = threadIdx.x;
    const int tx = tid & 15, ty = tid >> 4;
    const int bh = blockIdx.y;           // b*H + h
    const int b  = bh >> 3;
    const int h  = bh & 7;
    const int n0 = blockIdx.x << 6;

    // Load Q tile, transposed into Qs[d][r] (swizzled)
    const float* qb = g_q + ((size_t)bh * Nq + n0) * HD;
    {
        const int c4 = (tid & 15) << 2;      // d base
        #pragma unroll
        for (int i = 0; i < 4; ++i) {
            const int r = (tid >> 4) + (i << 4);
            float4 v = *(const float4*)(qb + r * HD + c4);
            Qs[swz(c4 + 0, r)] = v.x;
            Qs[swz(c4 + 1, r)] = v.y;
            Qs[swz(c4 + 2, r)] = v.z;
            Qs[swz(c4 + 3, r)] = v.w;
        }
    }

    float o[4][4] = {};
    float mrun[4], lrun[4];
    #pragma unroll
    for (int i = 0; i < 4; ++i) { mrun[i] = -1e30f; lrun[i] = 0.f; }

    const float* kb = g_k + (size_t)bh * Nkv * HD;
    const float* vb = g_v + (size_t)bh * Nkv * HD;
    const int* mb = kpm + b * Nkv;       // mask is bool promoted to int32

    for (int t = 0; t < Nkv; t += 64) {
        __syncthreads();   // previous PV done before overwriting KPs/Vs
        {
            const int c4 = (tid & 15) << 2;
            #pragma unroll
            for (int i = 0; i < 4; ++i) {
                const int r = (tid >> 4) + (i << 4);
                float4 kv = *(const float4*)(kb + (size_t)(t + r) * HD + c4);
                KPs[swz(c4 + 0, r)] = kv.x;
                KPs[swz(c4 + 1, r)] = kv.y;
                KPs[swz(c4 + 2, r)] = kv.z;
                KPs[swz(c4 + 3, r)] = kv.w;
                float4 vv = *(const float4*)(vb + (size_t)(t + r) * HD + c4);
                *(float4*)&Vs[r * 64 + c4] = vv;
            }
        }
        __syncthreads();

        // S = Q @ K^T  (rows r=4ty+i, cols c=4tx+j)
        float s[4][4] = {};
        #pragma unroll 8
        for (int d = 0; d < 64; ++d) {
            float4 q = *swp4(Qs,  d, ty);
            float4 k = *swp4(KPs, d, tx);
            float qa[4] = {q.x, q.y, q.z, q.w};
            float ka[4] = {k.x, k.y, k.z, k.w};
            #pragma unroll
            for (int i = 0; i < 4; ++i)
                #pragma unroll
                for (int j = 0; j < 4; ++j)
                    s[i][j] = fmaf(qa[i], ka[j], s[i][j]);
        }

        // scale + key padding mask (int32 bool: nonzero -> masked)
        float mk[4];
        #pragma unroll
        for (int j = 0; j < 4; ++j)
            mk[j] = mb[t + (tx << 2) + j] ? -1e30f : 0.f;
        #pragma unroll
        for (int i = 0; i < 4; ++i)
            #pragma unroll
            for (int j = 0; j < 4; ++j)
                s[i][j] = s[i][j] * SCALE + mk[j];

        // online softmax: row max / row sum via 16-lane xor shuffles
        #pragma unroll
        for (int i = 0; i < 4; ++i) {
            float v = fmaxf(fmaxf(s[i][0], s[i][1]), fmaxf(s[i][2], s[i][3]));
            #pragma unroll
            for (int off = 1; off < 16; off <<= 1)
                v = fmaxf(v, __shfl_xor_sync(0xffffffffu, v, off));
            const float mnew = fmaxf(mrun[i], v);
            const float corr = __expf(mrun[i] - mnew);
            mrun[i] = mnew;
            float rs = 0.f;
            #pragma unroll
            for (int j = 0; j < 4; ++j) {
                s[i][j] = __expf(s[i][j] - mnew);
                rs += s[i][j];
            }
            #pragma unroll
            for (int off = 1; off < 16; off <<= 1)
                rs += __shfl_xor_sync(0xffffffffu, rs, off);
            lrun[i] = lrun[i] * corr + rs;
            #pragma unroll
            for (int j = 0; j < 4; ++j)
                o[i][j] *= corr;
        }

        __syncthreads();   // all S reads of KPs done before P overwrites it
        #pragma unroll
        for (int i = 0; i < 4; ++i)
            #pragma unroll
            for (int j = 0; j < 4; ++j)
                KPs[swz((tx << 2) + j, (ty << 2) + i)] = s[i][j];  // Ps[c][r]
        __syncthreads();

        // O += P @ V
        #pragma unroll 8
        for (int c = 0; c < 64; ++c) {
            float4 p = *swp4(KPs, c, ty);
            float4 v = *(const float4*)&Vs[c * 64 + (tx << 2)];
            float pa[4] = {p.x, p.y, p.z, p.w};
            float va[4] = {v.x, v.y, v.z, v.w};
            #pragma unroll
            for (int i = 0; i < 4; ++i)
                #pragma unroll
                for (int j = 0; j < 4; ++j)
                    o[i][j] = fmaf(pa[i], va[j], o[i][j]);
        }
    }

    // normalize and write to [B,N,512] channel layout
    #pragma unroll
    for (int i = 0; i < 4; ++i) {
        const int r = n0 + (ty << 2) + i;
        const float inv = 1.f / lrun[i];
        #pragma unroll
        for (int j = 0; j < 4; ++j)
            g_o[((size_t)(b * Nq) + r) * DEC + (h << 6) + (tx << 2) + j] = o[i][j] * inv;
    }
}

// ---------------------------------------------------------------------------
extern "C" void kernel_launch(void* const* d_in, const int* in_sizes, int n_in,
                              void* d_out, int out_size)
{
    (void)in_sizes; (void)n_in; (void)out_size;
    const float* x   = (const float*)d_in[0];
    const float* y   = (const float*)d_in[1];
    const int*   kpm = (const int*)d_in[2];     // bool mask promoted to int32
    const float* Wq  = (const float*)d_in[3];
    const float* Wkv = (const float*)d_in[4];
    const float* Wp  = (const float*)d_in[5];
    const float* bp  = (const float*)d_in[6];
    float* out = (float*)d_out;

    // 1) Q projection + head reshuffle
    gemm_nt<0, DEC><<<dim3(DEC / 64, Bsz * Nq / 64), 256>>>(x, Wq, nullptr, nullptr);
    // 2) KV projection + split/head reshuffle
    gemm_nt<1, ENC><<<dim3(2 * DEC / 64, Bsz * Nkv / 64), 256>>>(y, Wkv, nullptr, nullptr);
    // 3) fused flash attention
    attn_kernel<<<dim3(Nq / 64, Bsz * NH), 256>>>(kpm);
    // 4) output projection + bias
    gemm_nt<2, DEC><<<dim3(DEC / 64, Bsz * Nq / 64), 256>>>(nullptr, Wp, out, bp);
}

// round 6
// speedup vs baseline: 1.9547x; 1.9547x over previous
#include <cuda_runtime.h>

#define DI __device__ __forceinline__

namespace {
constexpr int Bsz = 2;
constexpr int Nq  = 4096;
constexpr int Nkv = 4096;
constexpr int ENC = 768;
constexpr int DEC = 512;
constexpr int NH  = 8;
constexpr int HD  = 64;
constexpr float SCALE = 0.125f;  // 64^-0.5
}

// Scratch (allocation-free: static device globals)
__device__ float g_q[(size_t)Bsz * NH * Nq  * HD];  // [B,H,N,64]
__device__ float g_k[(size_t)Bsz * NH * Nkv * HD];  // [B,H,Ny,64]
__device__ float g_v[(size_t)Bsz * NH * Nkv * HD];  // [B,H,Ny,64]
__device__ float g_o[(size_t)Bsz * Nq * DEC];       // [B,N,512]

// ---------------------------------------------------------------------------
// GEMM-NT (fp32 FFMA, unchanged from passing R5 kernel)
// ---------------------------------------------------------------------------
template<int MODE, int K>
__global__ __launch_bounds__(256) void gemm_nt(const float* __restrict__ A,
                                               const float* __restrict__ Bw,
                                               float* __restrict__ Cout,
                                               const float* __restrict__ bias)
{
    __shared__ __align__(16) float As[16][68];
    __shared__ __align__(16) float Bs[16][68];
    const int tid = threadIdx.x;
    const int tx = tid & 15, ty = tid >> 4;
    const int m0 = blockIdx.y * 64;
    const int n0 = blockIdx.x * 64;
    const int lrow = tid >> 2;
    const int lk   = (tid & 3) << 2;

    const float* Abase = (MODE == 2) ? g_o : A;
    const float* aptr = Abase + (size_t)(m0 + lrow) * K + lk;
    const float* bptr = Bw    + (size_t)(n0 + lrow) * K + lk;

    float acc[4][4] = {};

    for (int k0 = 0; k0 < K; k0 += 16) {
        float4 av = *(const float4*)(aptr + k0);
        float4 bv = *(const float4*)(bptr + k0);
        __syncthreads();
        As[lk+0][lrow] = av.x; As[lk+1][lrow] = av.y;
        As[lk+2][lrow] = av.z; As[lk+3][lrow] = av.w;
        Bs[lk+0][lrow] = bv.x; Bs[lk+1][lrow] = bv.y;
        Bs[lk+2][lrow] = bv.z; Bs[lk+3][lrow] = bv.w;
        __syncthreads();
        #pragma unroll
        for (int k = 0; k < 16; ++k) {
            float4 a = *(const float4*)&As[k][ty << 2];
            float4 b = *(const float4*)&Bs[k][tx << 2];
            float ar[4] = {a.x, a.y, a.z, a.w};
            float br[4] = {b.x, b.y, b.z, b.w};
            #pragma unroll
            for (int i = 0; i < 4; ++i)
                #pragma unroll
                for (int j = 0; j < 4; ++j)
                    acc[i][j] = fmaf(ar[i], br[j], acc[i][j]);
        }
    }

    #pragma unroll
    for (int i = 0; i < 4; ++i) {
        const int m = m0 + (ty << 2) + i;
        #pragma unroll
        for (int j = 0; j < 4; ++j) {
            const int n = n0 + (tx << 2) + j;
            const float v = acc[i][j];
            if (MODE == 0) {
                const int b = m >> 12, nn = m & 4095, h = n >> 6, d = n & 63;
                g_q[(((size_t)(b * NH + h)) * Nq + nn) * HD + d] = v;
            } else if (MODE == 1) {
                const int b = m >> 12, nn = m & 4095;
                if (n < DEC) {
                    const int h = n >> 6, d = n & 63;
                    g_k[(((size_t)(b * NH + h)) * Nkv + nn) * HD + d] = v;
                } else {
                    const int n2 = n - DEC, h = n2 >> 6, d = n2 & 63;
                    g_v[(((size_t)(b * NH + h)) * Nkv + nn) * HD + d] = v;
                }
            } else {
                Cout[(size_t)m * DEC + n] = v + bias[n];
            }
        }
    }
}

// ---------------------------------------------------------------------------
// Tensor-core flash attention (tf32 mma.sync.m16n8k8)
// Block = 256 threads = 8 warps; Q block 128 rows; warp w owns rows [16w,16w+16).
// KV tile = 64 keys. K/V in smem (tf32 bits, stride 72: conflict-free frags).
// Q lives in A-fragments in registers. P C-frag -> A-frag via shuffles.
// ---------------------------------------------------------------------------
DI unsigned f2tf(float x) {
    unsigned r;
    asm("cvt.rna.tf32.f32 %0, %1;" : "=r"(r) : "f"(x));
    return r;
}

DI void mma_tf32(float c[4], unsigned a0, unsigned a1, unsigned a2, unsigned a3,
                 unsigned b0, unsigned b1) {
    asm volatile(
        "mma.sync.aligned.m16n8k8.row.col.f32.tf32.tf32.f32 "
        "{%0,%1,%2,%3}, {%4,%5,%6,%7}, {%8,%9}, {%0,%1,%2,%3};"
        : "+f"(c[0]), "+f"(c[1]), "+f"(c[2]), "+f"(c[3])
        : "r"(a0), "r"(a1), "r"(a2), "r"(a3), "r"(b0), "r"(b1));
}

__global__ __launch_bounds__(256, 2) void attn_kernel(const int* __restrict__ kpm)
{
    __shared__ __align__(16) unsigned Ku[64 * 72];
    __shared__ __align__(16) unsigned Vu[64 * 72];
    __shared__ float Msk[64];

    const int tid  = threadIdx.x;
    const int w    = tid >> 5;
    const int lane = tid & 31;
    const int g    = lane >> 2;   // groupID (row within m16 strip)
    const int c    = lane & 3;    // threadID_in_group
    const int bh   = blockIdx.y;
    const int b    = bh >> 3;
    const int h    = bh & 7;
    const int n0   = blockIdx.x << 7;   // 128-row Q block

    const float NEG_INF = __int_as_float(0xff800000);

    const float* qb = g_q + ((size_t)bh * Nq + n0) * HD;
    const float* kb = g_k + (size_t)bh * Nkv * HD;
    const float* vb = g_v + (size_t)bh * Nkv * HD;
    const int*   mb = kpm + b * Nkv;

    // ---- Stage Q (128x64) through Ku/Vu, then pull A-frags to registers ----
    #pragma unroll
    for (int u = 0; u < 8; ++u) {
        const int chunk = tid + 256 * u;         // 0..2047
        const int row = chunk >> 4;
        const int c4  = (chunk & 15) << 2;
        float4 qv = *(const float4*)(qb + (size_t)row * HD + c4);
        uint4 qt = {f2tf(qv.x), f2tf(qv.y), f2tf(qv.z), f2tf(qv.w)};
        unsigned* dst = (row < 64 ? Ku + row * 72 : Vu + (row - 64) * 72) + c4;
        *(uint4*)dst = qt;
    }
    __syncthreads();

    unsigned qa[8][4];
    {
        const unsigned* Qb = (w < 4) ? Ku : Vu;
        const int rb = (w * 16) & 63;
        #pragma unroll
        for (int kk = 0; kk < 8; ++kk) {
            qa[kk][0] = Qb[(rb + g    ) * 72 + kk * 8 + c];
            qa[kk][1] = Qb[(rb + g + 8) * 72 + kk * 8 + c];
            qa[kk][2] = Qb[(rb + g    ) * 72 + kk * 8 + c + 4];
            qa[kk][3] = Qb[(rb + g + 8) * 72 + kk * 8 + c + 4];
        }
    }

    float o[8][4] = {};
    float mr0 = -1e30f, mr1 = -1e30f, l0 = 0.f, l1 = 0.f;

    const int srcA = (lane & ~3) | ((lane & 3) >> 1);
    const int srcB = srcA + 2;
    const bool odd = lane & 1;

    for (int t = 0; t < Nkv; t += 64) {
        __syncthreads();   // prior-iter smem reads done before restaging

        // ---- stage K/V tile (tf32) + mask ----
        #pragma unroll
        for (int u = 0; u < 4; ++u) {
            const int chunk = tid + 256 * u;     // 0..1023
            const int row = chunk >> 4;
            const int c4  = (chunk & 15) << 2;
            float4 kv = *(const float4*)(kb + (size_t)(t + row) * HD + c4);
            uint4 kt = {f2tf(kv.x), f2tf(kv.y), f2tf(kv.z), f2tf(kv.w)};
            *(uint4*)(Ku + row * 72 + c4) = kt;
            float4 vv = *(const float4*)(vb + (size_t)(t + row) * HD + c4);
            uint4 vt = {f2tf(vv.x), f2tf(vv.y), f2tf(vv.z), f2tf(vv.w)};
            *(uint4*)(Vu + row * 72 + c4) = vt;
        }
        if (tid < 64) Msk[tid] = mb[t + tid] ? NEG_INF : 0.f;
        __syncthreads();

        // ---- S = Q @ K^T ----
        float s[8][4] = {};
        #pragma unroll
        for (int kk = 0; kk < 8; ++kk) {
            #pragma unroll
            for (int j = 0; j < 8; ++j) {
                unsigned b0 = Ku[(j * 8 + g) * 72 + kk * 8 + c];
                unsigned b1 = Ku[(j * 8 + g) * 72 + kk * 8 + c + 4];
                mma_tf32(s[j], qa[kk][0], qa[kk][1], qa[kk][2], qa[kk][3], b0, b1);
            }
        }

        // ---- scale + mask + online softmax (rows g and g+8, warp-local) ----
        float vm0 = -1e30f, vm1 = -1e30f;
        #pragma unroll
        for (int j = 0; j < 8; ++j) {
            const float mk0 = Msk[j * 8 + 2 * c];
            const float mk1 = Msk[j * 8 + 2 * c + 1];
            s[j][0] = fmaf(s[j][0], SCALE, mk0);
            s[j][1] = fmaf(s[j][1], SCALE, mk1);
            s[j][2] = fmaf(s[j][2], SCALE, mk0);
            s[j][3] = fmaf(s[j][3], SCALE, mk1);
            vm0 = fmaxf(vm0, fmaxf(s[j][0], s[j][1]));
            vm1 = fmaxf(vm1, fmaxf(s[j][2], s[j][3]));
        }
        vm0 = fmaxf(vm0, __shfl_xor_sync(0xffffffffu, vm0, 1));
        vm0 = fmaxf(vm0, __shfl_xor_sync(0xffffffffu, vm0, 2));
        vm1 = fmaxf(vm1, __shfl_xor_sync(0xffffffffu, vm1, 1));
        vm1 = fmaxf(vm1, __shfl_xor_sync(0xffffffffu, vm1, 2));

        const float mn0 = fmaxf(mr0, vm0);
        const float mn1 = fmaxf(mr1, vm1);
        const float cr0 = __expf(mr0 - mn0);
        const float cr1 = __expf(mr1 - mn1);
        mr0 = mn0; mr1 = mn1;

        float rs0 = 0.f, rs1 = 0.f;
        #pragma unroll
        for (int j = 0; j < 8; ++j) {
            s[j][0] = __expf(s[j][0] - mn0);
            s[j][1] = __expf(s[j][1] - mn0);
            s[j][2] = __expf(s[j][2] - mn1);
            s[j][3] = __expf(s[j][3] - mn1);
            rs0 += s[j][0] + s[j][1];
            rs1 += s[j][2] + s[j][3];
        }
        rs0 += __shfl_xor_sync(0xffffffffu, rs0, 1);
        rs0 += __shfl_xor_sync(0xffffffffu, rs0, 2);
        rs1 += __shfl_xor_sync(0xffffffffu, rs1, 1);
        rs1 += __shfl_xor_sync(0xffffffffu, rs1, 2);
        l0 = l0 * cr0 + rs0;
        l1 = l1 * cr1 + rs1;

        #pragma unroll
        for (int j = 0; j < 8; ++j) {
            o[j][0] *= cr0; o[j][1] *= cr0;
            o[j][2] *= cr1; o[j][3] *= cr1;
        }

        // ---- O += P @ V : P C-frag -> A-frag via shuffles, V B-frag from smem
        #pragma unroll
        for (int kk = 0; kk < 8; ++kk) {     // kk = key 8-block (= S's j)
            float t00 = __shfl_sync(0xffffffffu, s[kk][0], srcA);
            float t01 = __shfl_sync(0xffffffffu, s[kk][1], srcA);
            float t02 = __shfl_sync(0xffffffffu, s[kk][2], srcA);
            float t03 = __shfl_sync(0xffffffffu, s[kk][3], srcA);
            float u00 = __shfl_sync(0xffffffffu, s[kk][0], srcB);
            float u01 = __shfl_sync(0xffffffffu, s[kk][1], srcB);
            float u02 = __shfl_sync(0xffffffffu, s[kk][2], srcB);
            float u03 = __shfl_sync(0xffffffffu, s[kk][3], srcB);
            unsigned pa0 = f2tf(odd ? t01 : t00);   // (row g,   k=kk*8+c)
            unsigned pa1 = f2tf(odd ? t03 : t02);   // (row g+8, k=kk*8+c)
            unsigned pa2 = f2tf(odd ? u01 : u00);   // (row g,   k=kk*8+c+4)
            unsigned pa3 = f2tf(odd ? u03 : u02);   // (row g+8, k=kk*8+c+4)
            #pragma unroll
            for (int j = 0; j < 8; ++j) {
                unsigned b0 = Vu[(kk * 8 + c    ) * 72 + j * 8 + g];
                unsigned b1 = Vu[(kk * 8 + c + 4) * 72 + j * 8 + g];
                mma_tf32(o[j], pa0, pa1, pa2, pa3, b0, b1);
            }
        }
    }

    // ---- normalize + write to [B,N,512] ----
    const float inv0 = 1.f / l0;
    const float inv1 = 1.f / l1;
    float* ob = g_o + ((size_t)(b * Nq) + n0 + w * 16) * DEC + h * 64;
    #pragma unroll
    for (int j = 0; j < 8; ++j) {
        float2 v0 = {o[j][0] * inv0, o[j][1] * inv0};
        float2 v1 = {o[j][2] * inv1, o[j][3] * inv1};
        *(float2*)(ob + (size_t)g * DEC + j * 8 + 2 * c)       = v0;
        *(float2*)(ob + (size_t)(g + 8) * DEC + j * 8 + 2 * c) = v1;
    }
}

// ---------------------------------------------------------------------------
extern "C" void kernel_launch(void* const* d_in, const int* in_sizes, int n_in,
                              void* d_out, int out_size)
{
    (void)in_sizes; (void)n_in; (void)out_size;
    const float* x   = (const float*)d_in[0];
    const float* y   = (const float*)d_in[1];
    const int*   kpm = (const int*)d_in[2];     // bool mask promoted to int32
    const float* Wq  = (const float*)d_in[3];
    const float* Wkv = (const float*)d_in[4];
    const float* Wp  = (const float*)d_in[5];
    const float* bp  = (const float*)d_in[6];
    float* out = (float*)d_out;

    gemm_nt<0, DEC><<<dim3(DEC / 64, Bsz * Nq / 64), 256>>>(x, Wq, nullptr, nullptr);
    gemm_nt<1, ENC><<<dim3(2 * DEC / 64, Bsz * Nkv / 64), 256>>>(y, Wkv, nullptr, nullptr);
    attn_kernel<<<dim3(Nq / 128, Bsz * NH), 256>>>(kpm);
    gemm_nt<2, DEC><<<dim3(DEC / 64, Bsz * Nq / 64), 256>>>(nullptr, Wp, out, bp);
}

// round 7
// speedup vs baseline: 2.7583x; 1.4111x over previous
#include <cuda_runtime.h>

#define DI __device__ __forceinline__

namespace {
constexpr int Bsz = 2;
constexpr int Nq  = 4096;
constexpr int Nkv = 4096;
constexpr int ENC = 768;
constexpr int DEC = 512;
constexpr int NH  = 8;
constexpr int HD  = 64;
constexpr float SCALE = 0.125f;  // 64^-0.5
}

// Scratch (allocation-free: static device globals)
__device__ float g_q[(size_t)Bsz * NH * Nq  * HD];  // [B,H,N,64]
__device__ float g_k[(size_t)Bsz * NH * Nkv * HD];  // [B,H,Ny,64]
__device__ float g_v[(size_t)Bsz * NH * Nkv * HD];  // [B,H,Ny,64]
__device__ float g_o[(size_t)Bsz * Nq * DEC];       // [B,N,512]

DI unsigned f2tf(float x) {
    unsigned r;
    asm("cvt.rna.tf32.f32 %0, %1;" : "=r"(r) : "f"(x));
    return r;
}

DI void mma_tf32(float c[4], unsigned a0, unsigned a1, unsigned a2, unsigned a3,
                 unsigned b0, unsigned b1) {
    asm volatile(
        "mma.sync.aligned.m16n8k8.row.col.f32.tf32.tf32.f32 "
        "{%0,%1,%2,%3}, {%4,%5,%6,%7}, {%8,%9}, {%0,%1,%2,%3};"
        : "+f"(c[0]), "+f"(c[1]), "+f"(c[2]), "+f"(c[3])
        : "r"(a0), "r"(a1), "r"(a2), "r"(a3), "r"(b0), "r"(b1));
}

// ---------------------------------------------------------------------------
// GEMM-NT on tensor pipe (tf32 m16n8k8): C[m][n] = sum_k A[m][k] * Bw[n][k]
// Block 256 thr = 8 warps. Tile BM=128 (16 rows/warp), BN=64, BK=32.
// MODE 0: A=x -> g_q reshuffle; MODE 1: A=y -> g_k/g_v; MODE 2: A=g_o -> out+bias
// ---------------------------------------------------------------------------
template<int MODE, int K>
__global__ __launch_bounds__(256, 2) void gemm_mma(const float* __restrict__ A,
                                                   const float* __restrict__ Bw,
                                                   float* __restrict__ Cout,
                                                   const float* __restrict__ bias)
{
    __shared__ __align__(16) unsigned As[128 * 36];
    __shared__ __align__(16) unsigned Bs[64 * 36];

    const int tid  = threadIdx.x;
    const int w    = tid >> 5;
    const int lane = tid & 31;
    const int g    = lane >> 2;
    const int c    = lane & 3;
    const int m0   = blockIdx.y << 7;   // 128-row tile
    const int n0   = blockIdx.x << 6;   // 64-col tile

    const float* Abase = (MODE == 2) ? g_o : A;

    float acc[8][4] = {};

    for (int k0 = 0; k0 < K; k0 += 32) {
        __syncthreads();   // prior-iter frag reads complete before restaging
        #pragma unroll
        for (int u = 0; u < 4; ++u) {              // A tile: 128 x 32
            const int idx = tid + 256 * u;
            const int row = idx >> 3;
            const int c4  = (idx & 7) << 2;
            float4 av = *(const float4*)(Abase + (size_t)(m0 + row) * K + k0 + c4);
            uint4 at = {f2tf(av.x), f2tf(av.y), f2tf(av.z), f2tf(av.w)};
            *(uint4*)(As + row * 36 + c4) = at;
        }
        #pragma unroll
        for (int u = 0; u < 2; ++u) {              // B tile: 64 x 32
            const int idx = tid + 256 * u;
            const int row = idx >> 3;
            const int c4  = (idx & 7) << 2;
            float4 bv = *(const float4*)(Bw + (size_t)(n0 + row) * K + k0 + c4);
            uint4 bt = {f2tf(bv.x), f2tf(bv.y), f2tf(bv.z), f2tf(bv.w)};
            *(uint4*)(Bs + row * 36 + c4) = bt;
        }
        __syncthreads();

        #pragma unroll
        for (int kk = 0; kk < 4; ++kk) {
            const unsigned a0 = As[(w * 16 + g    ) * 36 + kk * 8 + c];
            const unsigned a1 = As[(w * 16 + g + 8) * 36 + kk * 8 + c];
            const unsigned a2 = As[(w * 16 + g    ) * 36 + kk * 8 + c + 4];
            const unsigned a3 = As[(w * 16 + g + 8) * 36 + kk * 8 + c + 4];
            #pragma unroll
            for (int j = 0; j < 8; ++j) {
                const unsigned b0 = Bs[(j * 8 + g) * 36 + kk * 8 + c];
                const unsigned b1 = Bs[(j * 8 + g) * 36 + kk * 8 + c + 4];
                mma_tf32(acc[j], a0, a1, a2, a3, b0, b1);
            }
        }
    }

    // Epilogue: thread holds rows (w*16+g, +8), cols n0 + j*8 + 2c (+1)
    #pragma unroll
    for (int j = 0; j < 8; ++j) {
        const int n = n0 + j * 8 + 2 * c;
        #pragma unroll
        for (int half = 0; half < 2; ++half) {
            const int m = m0 + w * 16 + g + half * 8;
            float2 val = {acc[j][2 * half], acc[j][2 * half + 1]};
            if (MODE == 0) {
                const int b = m >> 12, nn = m & 4095, h = n >> 6, d = n & 63;
                *(float2*)&g_q[(((size_t)(b * NH + h)) * Nq + nn) * HD + d] = val;
            } else if (MODE == 1) {
                const int b = m >> 12, nn = m & 4095;
                if (n < DEC) {
                    const int h = n >> 6, d = n & 63;
                    *(float2*)&g_k[(((size_t)(b * NH + h)) * Nkv + nn) * HD + d] = val;
                } else {
                    const int n2 = n - DEC, h = n2 >> 6, d = n2 & 63;
                    *(float2*)&g_v[(((size_t)(b * NH + h)) * Nkv + nn) * HD + d] = val;
                }
            } else {
                float2 bb = *(const float2*)&bias[n];
                val.x += bb.x; val.y += bb.y;
                *(float2*)&Cout[(size_t)m * DEC + n] = val;
            }
        }
    }
}

// ---------------------------------------------------------------------------
// Tensor-core flash attention (tf32 mma.sync.m16n8k8) — unchanged from R6
// ---------------------------------------------------------------------------
__global__ __launch_bounds__(256, 2) void attn_kernel(const int* __restrict__ kpm)
{
    __shared__ __align__(16) unsigned Ku[64 * 72];
    __shared__ __align__(16) unsigned Vu[64 * 72];
    __shared__ float Msk[64];

    const int tid  = threadIdx.x;
    const int w    = tid >> 5;
    const int lane = tid & 31;
    const int g    = lane >> 2;
    const int c    = lane & 3;
    const int bh   = blockIdx.y;
    const int b    = bh >> 3;
    const int h    = bh & 7;
    const int n0   = blockIdx.x << 7;

    const float NEG_INF = __int_as_float(0xff800000);

    const float* qb = g_q + ((size_t)bh * Nq + n0) * HD;
    const float* kb = g_k + (size_t)bh * Nkv * HD;
    const float* vb = g_v + (size_t)bh * Nkv * HD;
    const int*   mb = kpm + b * Nkv;

    #pragma unroll
    for (int u = 0; u < 8; ++u) {
        const int chunk = tid + 256 * u;
        const int row = chunk >> 4;
        const int c4  = (chunk & 15) << 2;
        float4 qv = *(const float4*)(qb + (size_t)row * HD + c4);
        uint4 qt = {f2tf(qv.x), f2tf(qv.y), f2tf(qv.z), f2tf(qv.w)};
        unsigned* dst = (row < 64 ? Ku + row * 72 : Vu + (row - 64) * 72) + c4;
        *(uint4*)dst = qt;
    }
    __syncthreads();

    unsigned qa[8][4];
    {
        const unsigned* Qb = (w < 4) ? Ku : Vu;
        const int rb = (w * 16) & 63;
        #pragma unroll
        for (int kk = 0; kk < 8; ++kk) {
            qa[kk][0] = Qb[(rb + g    ) * 72 + kk * 8 + c];
            qa[kk][1] = Qb[(rb + g + 8) * 72 + kk * 8 + c];
            qa[kk][2] = Qb[(rb + g    ) * 72 + kk * 8 + c + 4];
            qa[kk][3] = Qb[(rb + g + 8) * 72 + kk * 8 + c + 4];
        }
    }

    float o[8][4] = {};
    float mr0 = -1e30f, mr1 = -1e30f, l0 = 0.f, l1 = 0.f;

    const int srcA = (lane & ~3) | ((lane & 3) >> 1);
    const int srcB = srcA + 2;
    const bool odd = lane & 1;

    for (int t = 0; t < Nkv; t += 64) {
        __syncthreads();

        #pragma unroll
        for (int u = 0; u < 4; ++u) {
            const int chunk = tid + 256 * u;
            const int row = chunk >> 4;
            const int c4  = (chunk & 15) << 2;
            float4 kv = *(const float4*)(kb + (size_t)(t + row) * HD + c4);
            uint4 kt = {f2tf(kv.x), f2tf(kv.y), f2tf(kv.z), f2tf(kv.w)};
            *(uint4*)(Ku + row * 72 + c4) = kt;
            float4 vv = *(const float4*)(vb + (size_t)(t + row) * HD + c4);
            uint4 vt = {f2tf(vv.x), f2tf(vv.y), f2tf(vv.z), f2tf(vv.w)};
            *(uint4*)(Vu + row * 72 + c4) = vt;
        }
        if (tid < 64) Msk[tid] = mb[t + tid] ? NEG_INF : 0.f;
        __syncthreads();

        float s[8][4] = {};
        #pragma unroll
        for (int kk = 0; kk < 8; ++kk) {
            #pragma unroll
            for (int j = 0; j < 8; ++j) {
                unsigned b0 = Ku[(j * 8 + g) * 72 + kk * 8 + c];
                unsigned b1 = Ku[(j * 8 + g) * 72 + kk * 8 + c + 4];
                mma_tf32(s[j], qa[kk][0], qa[kk][1], qa[kk][2], qa[kk][3], b0, b1);
            }
        }

        float vm0 = -1e30f, vm1 = -1e30f;
        #pragma unroll
        for (int j = 0; j < 8; ++j) {
            const float mk0 = Msk[j * 8 + 2 * c];
            const float mk1 = Msk[j * 8 + 2 * c + 1];
            s[j][0] = fmaf(s[j][0], SCALE, mk0);
            s[j][1] = fmaf(s[j][1], SCALE, mk1);
            s[j][2] = fmaf(s[j][2], SCALE, mk0);
            s[j][3] = fmaf(s[j][3], SCALE, mk1);
            vm0 = fmaxf(vm0, fmaxf(s[j][0], s[j][1]));
            vm1 = fmaxf(vm1, fmaxf(s[j][2], s[j][3]));
        }
        vm0 = fmaxf(vm0, __shfl_xor_sync(0xffffffffu, vm0, 1));
        vm0 = fmaxf(vm0, __shfl_xor_sync(0xffffffffu, vm0, 2));
        vm1 = fmaxf(vm1, __shfl_xor_sync(0xffffffffu, vm1, 1));
        vm1 = fmaxf(vm1, __shfl_xor_sync(0xffffffffu, vm1, 2));

        const float mn0 = fmaxf(mr0, vm0);
        const float mn1 = fmaxf(mr1, vm1);
        const float cr0 = __expf(mr0 - mn0);
        const float cr1 = __expf(mr1 - mn1);
        mr0 = mn0; mr1 = mn1;

        float rs0 = 0.f, rs1 = 0.f;
        #pragma unroll
        for (int j = 0; j < 8; ++j) {
            s[j][0] = __expf(s[j][0] - mn0);
            s[j][1] = __expf(s[j][1] - mn0);
            s[j][2] = __expf(s[j][2] - mn1);
            s[j][3] = __expf(s[j][3] - mn1);
            rs0 += s[j][0] + s[j][1];
            rs1 += s[j][2] + s[j][3];
        }
        rs0 += __shfl_xor_sync(0xffffffffu, rs0, 1);
        rs0 += __shfl_xor_sync(0xffffffffu, rs0, 2);
        rs1 += __shfl_xor_sync(0xffffffffu, rs1, 1);
        rs1 += __shfl_xor_sync(0xffffffffu, rs1, 2);
        l0 = l0 * cr0 + rs0;
        l1 = l1 * cr1 + rs1;

        #pragma unroll
        for (int j = 0; j < 8; ++j) {
            o[j][0] *= cr0; o[j][1] *= cr0;
            o[j][2] *= cr1; o[j][3] *= cr1;
        }

        #pragma unroll
        for (int kk = 0; kk < 8; ++kk) {
            float t00 = __shfl_sync(0xffffffffu, s[kk][0], srcA);
            float t01 = __shfl_sync(0xffffffffu, s[kk][1], srcA);
            float t02 = __shfl_sync(0xffffffffu, s[kk][2], srcA);
            float t03 = __shfl_sync(0xffffffffu, s[kk][3], srcA);
            float u00 = __shfl_sync(0xffffffffu, s[kk][0], srcB);
            float u01 = __shfl_sync(0xffffffffu, s[kk][1], srcB);
            float u02 = __shfl_sync(0xffffffffu, s[kk][2], srcB);
            float u03 = __shfl_sync(0xffffffffu, s[kk][3], srcB);
            unsigned pa0 = f2tf(odd ? t01 : t00);
            unsigned pa1 = f2tf(odd ? t03 : t02);
            unsigned pa2 = f2tf(odd ? u01 : u00);
            unsigned pa3 = f2tf(odd ? u03 : u02);
            #pragma unroll
            for (int j = 0; j < 8; ++j) {
                unsigned b0 = Vu[(kk * 8 + c    ) * 72 + j * 8 + g];
                unsigned b1 = Vu[(kk * 8 + c + 4) * 72 + j * 8 + g];
                mma_tf32(o[j], pa0, pa1, pa2, pa3, b0, b1);
            }
        }
    }

    const float inv0 = 1.f / l0;
    const float inv1 = 1.f / l1;
    float* ob = g_o + ((size_t)(b * Nq) + n0 + w * 16) * DEC + h * 64;
    #pragma unroll
    for (int j = 0; j < 8; ++j) {
        float2 v0 = {o[j][0] * inv0, o[j][1] * inv0};
        float2 v1 = {o[j][2] * inv1, o[j][3] * inv1};
        *(float2*)(ob + (size_t)g * DEC + j * 8 + 2 * c)       = v0;
        *(float2*)(ob + (size_t)(g + 8) * DEC + j * 8 + 2 * c) = v1;
    }
}

// ---------------------------------------------------------------------------
extern "C" void kernel_launch(void* const* d_in, const int* in_sizes, int n_in,
                              void* d_out, int out_size)
{
    (void)in_sizes; (void)n_in; (void)out_size;
    const float* x   = (const float*)d_in[0];
    const float* y   = (const float*)d_in[1];
    const int*   kpm = (const int*)d_in[2];     // bool mask promoted to int32
    const float* Wq  = (const float*)d_in[3];
    const float* Wkv = (const float*)d_in[4];
    const float* Wp  = (const float*)d_in[5];
    const float* bp  = (const float*)d_in[6];
    float* out = (float*)d_out;

    gemm_mma<0, DEC><<<dim3(DEC / 64, Bsz * Nq / 128), 256>>>(x, Wq, nullptr, nullptr);
    gemm_mma<1, ENC><<<dim3(2 * DEC / 64, Bsz * Nkv / 128), 256>>>(y, Wkv, nullptr, nullptr);
    attn_kernel<<<dim3(Nq / 128, Bsz * NH), 256>>>(kpm);
    gemm_mma<2, DEC><<<dim3(DEC / 64, Bsz * Nq / 128), 256>>>(nullptr, Wp, out, bp);
}

// round 8
// speedup vs baseline: 4.3333x; 1.5710x over previous
#include <cuda_runtime.h>

#define DI __device__ __forceinline__

namespace {
constexpr int Bsz = 2;
constexpr int Nq  = 4096;
constexpr int Nkv = 4096;
constexpr int ENC = 768;
constexpr int DEC = 512;
constexpr int NH  = 8;
constexpr int HD  = 64;
constexpr float SCALE = 0.125f;                       // 64^-0.5
constexpr float SCALE_L2E = 0.125f * 1.4426950408889634f;  // SCALE * log2(e)
}

// Scratch (allocation-free: static device globals)
__device__ float g_q[(size_t)Bsz * NH * Nq  * HD];  // [B,H,N,64]
__device__ float g_k[(size_t)Bsz * NH * Nkv * HD];  // [B,H,Ny,64]
__device__ float g_v[(size_t)Bsz * NH * Nkv * HD];  // [B,H,Ny,64]
__device__ float g_o[(size_t)Bsz * Nq * DEC];       // [B,N,512]

DI unsigned f2tf(float x) {
    unsigned r;
    asm("cvt.rna.tf32.f32 %0, %1;" : "=r"(r) : "f"(x));
    return r;
}

DI unsigned packbf(float hi, float lo) {   // word = {lo, hi} bf16x2
    unsigned r;
    asm("cvt.rn.bf16x2.f32 %0, %1, %2;" : "=r"(r) : "f"(hi), "f"(lo));
    return r;
}

DI float ex2(float x) {
    float r;
    asm("ex2.approx.ftz.f32 %0, %1;" : "=f"(r) : "f"(x));
    return r;
}

DI void mma_tf32(float c[4], unsigned a0, unsigned a1, unsigned a2, unsigned a3,
                 unsigned b0, unsigned b1) {
    asm volatile(
        "mma.sync.aligned.m16n8k8.row.col.f32.tf32.tf32.f32 "
        "{%0,%1,%2,%3}, {%4,%5,%6,%7}, {%8,%9}, {%0,%1,%2,%3};"
        : "+f"(c[0]), "+f"(c[1]), "+f"(c[2]), "+f"(c[3])
        : "r"(a0), "r"(a1), "r"(a2), "r"(a3), "r"(b0), "r"(b1));
}

DI void mma_bf16(float c[4], unsigned a0, unsigned a1, unsigned a2, unsigned a3,
                 unsigned b0, unsigned b1) {
    asm volatile(
        "mma.sync.aligned.m16n8k16.row.col.f32.bf16.bf16.f32 "
        "{%0,%1,%2,%3}, {%4,%5,%6,%7}, {%8,%9}, {%0,%1,%2,%3};"
        : "+f"(c[0]), "+f"(c[1]), "+f"(c[2]), "+f"(c[3])
        : "r"(a0), "r"(a1), "r"(a2), "r"(a3), "r"(b0), "r"(b1));
}

// ---------------------------------------------------------------------------
// GEMM-NT on tensor pipe (tf32 m16n8k8) — unchanged from R7 (passing)
// ---------------------------------------------------------------------------
template<int MODE, int K>
__global__ __launch_bounds__(256, 2) void gemm_mma(const float* __restrict__ A,
                                                   const float* __restrict__ Bw,
                                                   float* __restrict__ Cout,
                                                   const float* __restrict__ bias)
{
    __shared__ __align__(16) unsigned As[128 * 36];
    __shared__ __align__(16) unsigned Bs[64 * 36];

    const int tid  = threadIdx.x;
    const int w    = tid >> 5;
    const int lane = tid & 31;
    const int g    = lane >> 2;
    const int c    = lane & 3;
    const int m0   = blockIdx.y << 7;
    const int n0   = blockIdx.x << 6;

    const float* Abase = (MODE == 2) ? g_o : A;

    float acc[8][4] = {};

    for (int k0 = 0; k0 < K; k0 += 32) {
        __syncthreads();
        #pragma unroll
        for (int u = 0; u < 4; ++u) {
            const int idx = tid + 256 * u;
            const int row = idx >> 3;
            const int c4  = (idx & 7) << 2;
            float4 av = *(const float4*)(Abase + (size_t)(m0 + row) * K + k0 + c4);
            uint4 at = {f2tf(av.x), f2tf(av.y), f2tf(av.z), f2tf(av.w)};
            *(uint4*)(As + row * 36 + c4) = at;
        }
        #pragma unroll
        for (int u = 0; u < 2; ++u) {
            const int idx = tid + 256 * u;
            const int row = idx >> 3;
            const int c4  = (idx & 7) << 2;
            float4 bv = *(const float4*)(Bw + (size_t)(n0 + row) * K + k0 + c4);
            uint4 bt = {f2tf(bv.x), f2tf(bv.y), f2tf(bv.z), f2tf(bv.w)};
            *(uint4*)(Bs + row * 36 + c4) = bt;
        }
        __syncthreads();

        #pragma unroll
        for (int kk = 0; kk < 4; ++kk) {
            const unsigned a0 = As[(w * 16 + g    ) * 36 + kk * 8 + c];
            const unsigned a1 = As[(w * 16 + g + 8) * 36 + kk * 8 + c];
            const unsigned a2 = As[(w * 16 + g    ) * 36 + kk * 8 + c + 4];
            const unsigned a3 = As[(w * 16 + g + 8) * 36 + kk * 8 + c + 4];
            #pragma unroll
            for (int j = 0; j < 8; ++j) {
                const unsigned b0 = Bs[(j * 8 + g) * 36 + kk * 8 + c];
                const unsigned b1 = Bs[(j * 8 + g) * 36 + kk * 8 + c + 4];
                mma_tf32(acc[j], a0, a1, a2, a3, b0, b1);
            }
        }
    }

    #pragma unroll
    for (int j = 0; j < 8; ++j) {
        const int n = n0 + j * 8 + 2 * c;
        #pragma unroll
        for (int half = 0; half < 2; ++half) {
            const int m = m0 + w * 16 + g + half * 8;
            float2 val = {acc[j][2 * half], acc[j][2 * half + 1]};
            if (MODE == 0) {
                const int b = m >> 12, nn = m & 4095, h = n >> 6, d = n & 63;
                *(float2*)&g_q[(((size_t)(b * NH + h)) * Nq + nn) * HD + d] = val;
            } else if (MODE == 1) {
                const int b = m >> 12, nn = m & 4095;
                if (n < DEC) {
                    const int h = n >> 6, d = n & 63;
                    *(float2*)&g_k[(((size_t)(b * NH + h)) * Nkv + nn) * HD + d] = val;
                } else {
                    const int n2 = n - DEC, h = n2 >> 6, d = n2 & 63;
                    *(float2*)&g_v[(((size_t)(b * NH + h)) * Nkv + nn) * HD + d] = val;
                }
            } else {
                float2 bb = *(const float2*)&bias[n];
                val.x += bb.x; val.y += bb.y;
                *(float2*)&Cout[(size_t)m * DEC + n] = val;
            }
        }
    }
}

// ---------------------------------------------------------------------------
// Flash attention, bf16 mma.m16n8k16.
// Block 256 thr = 8 warps, 128 q-rows (16/warp), 64-key KV tiles.
// Kw: 64 keys x 32 bf16x2-words (dim pairs), pad 36  -> S B-frags, 1 LDS each.
// Vt: 64 dims x 32 bf16x2-words (key pairs), pad 36, col ^= (dim>>3)&7 swizzle
//     -> PV B-frags, 1 conflict-free LDS each.
// P C-frag == A-frag layout for k16 => NO shuffles, just bf16x2 packs.
// ---------------------------------------------------------------------------
__global__ __launch_bounds__(256, 2) void attn_kernel(const int* __restrict__ kpm)
{
    __shared__ __align__(16) unsigned Kw[64 * 36];
    __shared__ __align__(16) unsigned Vt[64 * 36];
    __shared__ float Msk[64];

    const int tid  = threadIdx.x;
    const int w    = tid >> 5;
    const int lane = tid & 31;
    const int g    = lane >> 2;
    const int c    = lane & 3;
    const int bh   = blockIdx.y;
    const int b    = bh >> 3;
    const int h    = bh & 7;
    const int n0   = blockIdx.x << 7;

    const float* qb = g_q + ((size_t)bh * Nq + n0) * HD;
    const float* kb = g_k + (size_t)bh * Nkv * HD;
    const float* vb = g_v + (size_t)bh * Nkv * HD;
    const int*   mb = kpm + b * Nkv;

    // ---- Stage Q (128x64) as bf16 words through Kw/Vt, pull A-frags ----
    #pragma unroll
    for (int u = 0; u < 8; ++u) {
        const int chunk = tid + 256 * u;        // 0..2047
        const int row = chunk >> 4;             // 0..127
        const int c4  = (chunk & 15) << 2;
        float4 qv = *(const float4*)(qb + (size_t)row * HD + c4);
        uint2 qt = {packbf(qv.y, qv.x), packbf(qv.w, qv.z)};
        unsigned* base = (row < 64) ? Kw : Vt;
        *(uint2*)(base + (row & 63) * 36 + (c4 >> 1)) = qt;
    }
    __syncthreads();

    unsigned qa[4][4];
    {
        const unsigned* Qb = (w < 4) ? Kw : Vt;
        const int rb = (w * 16) & 63;
        #pragma unroll
        for (int kk = 0; kk < 4; ++kk) {
            qa[kk][0] = Qb[(rb + g    ) * 36 + kk * 8 + c];
            qa[kk][1] = Qb[(rb + g + 8) * 36 + kk * 8 + c];
            qa[kk][2] = Qb[(rb + g    ) * 36 + kk * 8 + c + 4];
            qa[kk][3] = Qb[(rb + g + 8) * 36 + kk * 8 + c + 4];
        }
    }

    float o[8][4] = {};
    float mr0 = -1e30f, mr1 = -1e30f, l0 = 0.f, l1 = 0.f;

    for (int t = 0; t < Nkv; t += 64) {
        __syncthreads();   // prior-iter smem reads done before restaging

        // ---- stage K row-major bf16 pairs ----
        #pragma unroll
        for (int u = 0; u < 4; ++u) {
            const int chunk = tid + 256 * u;     // 0..1023
            const int row = chunk >> 4;          // key 0..63
            const int c4  = (chunk & 15) << 2;   // dim
            float4 kv = *(const float4*)(kb + (size_t)(t + row) * HD + c4);
            uint2 kt = {packbf(kv.y, kv.x), packbf(kv.w, kv.z)};
            *(uint2*)(Kw + row * 36 + (c4 >> 1)) = kt;
        }
        // ---- stage V transposed: word (dim, keypair), swizzled col ----
        #pragma unroll
        for (int u = 0; u < 2; ++u) {
            const int item = tid + 256 * u;      // 0..511
            const int d4 = item & 15;            // dim quad
            const int rp = item >> 4;            // key pair 0..31
            const float* v0 = vb + (size_t)(t + 2 * rp) * HD + d4 * 4;
            float4 a = *(const float4*)v0;
            float4 bq = *(const float4*)(v0 + HD);
            const int d0 = d4 * 4;
            Vt[(d0 + 0) * 36 + (rp ^ (((d0 + 0) >> 3) & 7))] = packbf(bq.x, a.x);
            Vt[(d0 + 1) * 36 + (rp ^ (((d0 + 1) >> 3) & 7))] = packbf(bq.y, a.y);
            Vt[(d0 + 2) * 36 + (rp ^ (((d0 + 2) >> 3) & 7))] = packbf(bq.z, a.z);
            Vt[(d0 + 3) * 36 + (rp ^ (((d0 + 3) >> 3) & 7))] = packbf(bq.w, a.w);
        }
        if (tid < 64) Msk[tid] = mb[t + tid] ? -1e30f : 0.f;
        __syncthreads();

        // ---- S = Q @ K^T (bf16 k16) ----
        float s[8][4] = {};
        #pragma unroll
        for (int kk = 0; kk < 4; ++kk) {
            #pragma unroll
            for (int j = 0; j < 8; ++j) {
                const unsigned b0 = Kw[(j * 8 + g) * 36 + kk * 8 + c];
                const unsigned b1 = Kw[(j * 8 + g) * 36 + kk * 8 + c + 4];
                mma_bf16(s[j], qa[kk][0], qa[kk][1], qa[kk][2], qa[kk][3], b0, b1);
            }
        }

        // ---- scale(log2 domain) + mask + online softmax ----
        float vm0 = -1e30f, vm1 = -1e30f;
        #pragma unroll
        for (int j = 0; j < 8; ++j) {
            const float mk0 = Msk[j * 8 + 2 * c];
            const float mk1 = Msk[j * 8 + 2 * c + 1];
            s[j][0] = fmaf(s[j][0], SCALE_L2E, mk0);
            s[j][1] = fmaf(s[j][1], SCALE_L2E, mk1);
            s[j][2] = fmaf(s[j][2], SCALE_L2E, mk0);
            s[j][3] = fmaf(s[j][3], SCALE_L2E, mk1);
            vm0 = fmaxf(vm0, fmaxf(s[j][0], s[j][1]));
            vm1 = fmaxf(vm1, fmaxf(s[j][2], s[j][3]));
        }
        vm0 = fmaxf(vm0, __shfl_xor_sync(0xffffffffu, vm0, 1));
        vm0 = fmaxf(vm0, __shfl_xor_sync(0xffffffffu, vm0, 2));
        vm1 = fmaxf(vm1, __shfl_xor_sync(0xffffffffu, vm1, 1));
        vm1 = fmaxf(vm1, __shfl_xor_sync(0xffffffffu, vm1, 2));

        const float mn0 = fmaxf(mr0, vm0);
        const float mn1 = fmaxf(mr1, vm1);
        const float cr0 = ex2(mr0 - mn0);
        const float cr1 = ex2(mr1 - mn1);
        mr0 = mn0; mr1 = mn1;

        float rs0 = 0.f, rs1 = 0.f;
        #pragma unroll
        for (int j = 0; j < 8; ++j) {
            s[j][0] = ex2(s[j][0] - mn0);
            s[j][1] = ex2(s[j][1] - mn0);
            s[j][2] = ex2(s[j][2] - mn1);
            s[j][3] = ex2(s[j][3] - mn1);
            rs0 += s[j][0] + s[j][1];
            rs1 += s[j][2] + s[j][3];
        }
        rs0 += __shfl_xor_sync(0xffffffffu, rs0, 1);
        rs0 += __shfl_xor_sync(0xffffffffu, rs0, 2);
        rs1 += __shfl_xor_sync(0xffffffffu, rs1, 1);
        rs1 += __shfl_xor_sync(0xffffffffu, rs1, 2);
        l0 = l0 * cr0 + rs0;
        l1 = l1 * cr1 + rs1;

        #pragma unroll
        for (int j = 0; j < 8; ++j) {
            o[j][0] *= cr0; o[j][1] *= cr0;
            o[j][2] *= cr1; o[j][3] *= cr1;
        }

        // ---- O += P @ V : P C-frag IS the k16 A-frag layout (no shuffles) ----
        #pragma unroll
        for (int kk = 0; kk < 4; ++kk) {
            const unsigned pa0 = packbf(s[2 * kk    ][1], s[2 * kk    ][0]);
            const unsigned pa1 = packbf(s[2 * kk    ][3], s[2 * kk    ][2]);
            const unsigned pa2 = packbf(s[2 * kk + 1][1], s[2 * kk + 1][0]);
            const unsigned pa3 = packbf(s[2 * kk + 1][3], s[2 * kk + 1][2]);
            #pragma unroll
            for (int j = 0; j < 8; ++j) {   // j = output-dim 8-block; row dim = j*8+g
                const unsigned b0 = Vt[(j * 8 + g) * 36 + ((kk * 8 + c    ) ^ j)];
                const unsigned b1 = Vt[(j * 8 + g) * 36 + ((kk * 8 + c + 4) ^ j)];
                mma_bf16(o[j], pa0, pa1, pa2, pa3, b0, b1);
            }
        }
    }

    // ---- normalize + write to [B,N,512] ----
    const float inv0 = 1.f / l0;
    const float inv1 = 1.f / l1;
    float* ob = g_o + ((size_t)(b * Nq) + n0 + w * 16) * DEC + h * 64;
    #pragma unroll
    for (int j = 0; j < 8; ++j) {
        float2 v0 = {o[j][0] * inv0, o[j][1] * inv0};
        float2 v1 = {o[j][2] * inv1, o[j][3] * inv1};
        *(float2*)(ob + (size_t)g * DEC + j * 8 + 2 * c)       = v0;
        *(float2*)(ob + (size_t)(g + 8) * DEC + j * 8 + 2 * c) = v1;
    }
}

// ---------------------------------------------------------------------------
extern "C" void kernel_launch(void* const* d_in, const int* in_sizes, int n_in,
                              void* d_out, int out_size)
{
    (void)in_sizes; (void)n_in; (void)out_size;
    const float* x   = (const float*)d_in[0];
    const float* y   = (const float*)d_in[1];
    const int*   kpm = (const int*)d_in[2];     // bool mask promoted to int32
    const float* Wq  = (const float*)d_in[3];
    const float* Wkv = (const float*)d_in[4];
    const float* Wp  = (const float*)d_in[5];
    const float* bp  = (const float*)d_in[6];
    float* out = (float*)d_out;

    gemm_mma<0, DEC><<<dim3(DEC / 64, Bsz * Nq / 128), 256>>>(x, Wq, nullptr, nullptr);
    gemm_mma<1, ENC><<<dim3(2 * DEC / 64, Bsz * Nkv / 128), 256>>>(y, Wkv, nullptr, nullptr);
    attn_kernel<<<dim3(Nq / 128, Bsz * NH), 256>>>(kpm);
    gemm_mma<2, DEC><<<dim3(DEC / 64, Bsz * Nq / 128), 256>>>(nullptr, Wp, out, bp);
}